// round 16
// baseline (speedup 1.0000x reference)
#include <cuda_runtime.h>
#include <cuda_fp16.h>
#include <cstring>

#define B_    2
#define C_    32
#define H_    128
#define W_    256
#define MAXD  12
#define D_    23            // 2*MAXD - 1
#define HW    (H_ * W_)
#define WT    128           // threads per CTA (half row)
#define NO    4             // channel octs of 8
#define SW2   220           // window: 76 left halo + 128 + 16 right
#define HALO  76
#define DG    12            // disparities per split (d=11 computed by both)
#define TAPS  13            // DG + 1

__device__ __forceinline__ __half2 u2h2(unsigned u) {
    __half2 r; memcpy(&r, &u, 4); return r;
}

// out[b,d,h,w] = sum_c |feat_l[b,c,h,w] - (w0*fr[c,x0+d] + w1*fr[c,x0+d+1])|
// R11 exactly (fp16 8-channel octs, 13 x LDS.128 gather per oct, 1024 thin
// CTAs, symmetric d-splits, flush every oct) with ONE change: the oct loop
// is unrolled 2x so ptxas interleaves oct o+1's 13 LDS into oct o's ~200
// math instructions. Doubles each warp's in-flight LDS (MLP 13 -> 26),
// attacking the L1-queue latency equilibrium that R13/R14 showed is the
// real binder (cutting crossbar work or instruction count moved nothing).
// No added instructions, bit-identical math order per pixel.
__global__ __launch_bounds__(WT)
void cost_volume_kernel(const float* __restrict__ feat_l,
                        const float* __restrict__ feat_r,
                        const float* __restrict__ disp,
                        float* __restrict__ out)
{
    __shared__ __align__(16) uint4 s_o[NO][SW2];   // 14080 B

    const int xb    = blockIdx.x;        // 0..3 : (spl<<1)|half
    const int half_ = xb & 1;
    const int spl   = xb >> 1;
    const int h     = blockIdx.y;
    const int b     = blockIdx.z;
    const int tid   = threadIdx.x;
    const int W0    = half_ * WT;
    const int base  = W0 - HALO;         // global x of window index 0
    const int dlo   = spl * 11;          // 0 or 11

    // ---- stage zero-padded feat_r window as 8-channel octs (R11 fill) ----
    {
        const float* fr0 = feat_r + (((long)b * C_) * H_ + h) * W_;
        #pragma unroll
        for (int s = 0; s < 2; s++) {
            const int i = tid + s * WT;
            if (i < SW2) {
                const int gx = base + i;
                const bool v = (gx >= 0) & (gx < W_);
                const int gxc = v ? gx : 0;
                #pragma unroll
                for (int o = 0; o < NO; o++) {
                    const float a0 = v ? __ldg(fr0 + (2*o)      * HW + gxc) : 0.0f;
                    const float a1 = v ? __ldg(fr0 + (2*o + 1)  * HW + gxc) : 0.0f;
                    const float a2 = v ? __ldg(fr0 + (2*o + 16) * HW + gxc) : 0.0f;
                    const float a3 = v ? __ldg(fr0 + (2*o + 17) * HW + gxc) : 0.0f;
                    const float b0 = v ? __ldg(fr0 + (2*o + 8)  * HW + gxc) : 0.0f;
                    const float b1 = v ? __ldg(fr0 + (2*o + 9)  * HW + gxc) : 0.0f;
                    const float b2 = v ? __ldg(fr0 + (2*o + 24) * HW + gxc) : 0.0f;
                    const float b3 = v ? __ldg(fr0 + (2*o + 25) * HW + gxc) : 0.0f;
                    __half2 px = __floats2half2_rn(a0, a2);
                    __half2 py = __floats2half2_rn(a1, a3);
                    __half2 pz = __floats2half2_rn(b0, b2);
                    __half2 pw = __floats2half2_rn(b1, b3);
                    uint4 ov;
                    memcpy(&ov.x, &px, 4); memcpy(&ov.y, &py, 4);
                    memcpy(&ov.z, &pz, 4); memcpy(&ov.w, &pw, 4);
                    s_o[o][i] = ov;
                }
            }
        }
    }

    // ---- per-thread interpolation setup (overlaps fill) ----
    const int   w    = W0 + tid;
    const float dval = __ldg(disp + ((long)b * H_ + h) * W_ + w);
    const float px0  = ((float)w - dval) - (float)(MAXD - 1);
    const float xf   = floorf(px0);
    const float w1   = px0 - xf;          // right-neighbor weight (const over d)
    const float w0   = 1.0f - w1;
    int x0l = (int)xf - base;             // in [tid+1, tid+65]
    x0l = max(0, min(SW2 - 24, x0l));     // xs + 12 <= 219 for both splits
    const int xs = x0l + dlo;

    const __half2 nw0 = __float2half2_rn(-w0);
    const __half2 nw1 = __float2half2_rn(-w1);

    __syncthreads();

    float accf[DG];
    #pragma unroll
    for (int d = 0; d < DG; d++) accf[d] = 0.0f;

    const float* fl0 = feat_l + (((long)b * C_) * H_ + h) * W_ + w;

    #pragma unroll 2
    for (int o = 0; o < NO; o++) {                 // 4 octs (8 channels each)
        const float a0 = __ldg(fl0 + (2*o)      * HW);
        const float a1 = __ldg(fl0 + (2*o + 1)  * HW);
        const float a2 = __ldg(fl0 + (2*o + 16) * HW);
        const float a3 = __ldg(fl0 + (2*o + 17) * HW);
        const float b0 = __ldg(fl0 + (2*o + 8)  * HW);
        const float b1 = __ldg(fl0 + (2*o + 9)  * HW);
        const float b2 = __ldg(fl0 + (2*o + 24) * HW);
        const float b3 = __ldg(fl0 + (2*o + 25) * HW);
        const __half2 fX = __floats2half2_rn(a0, a2);
        const __half2 fY = __floats2half2_rn(a1, a3);
        const __half2 fZ = __floats2half2_rn(b0, b2);
        const __half2 fW = __floats2half2_rn(b1, b3);

        const uint4* row = &s_o[o][xs];
        uint4 t[TAPS];
        #pragma unroll
        for (int j = 0; j < TAPS; j++) t[j] = row[j];   // 13 x LDS.128

        __half2 acc2[DG];
        #pragma unroll
        for (int d = 0; d < DG; d++) acc2[d] = __float2half2_rn(0.0f);

        #pragma unroll
        for (int d = 0; d < DG; d++) {
            __half2 u0 = __hfma2(u2h2(t[d].x),     nw0, fX);
            u0         = __hfma2(u2h2(t[d + 1].x), nw1, u0);
            __half2 u1 = __hfma2(u2h2(t[d].y),     nw0, fY);
            u1         = __hfma2(u2h2(t[d + 1].y), nw1, u1);
            __half2 u2 = __hfma2(u2h2(t[d].z),     nw0, fZ);
            u2         = __hfma2(u2h2(t[d + 1].z), nw1, u2);
            __half2 u3 = __hfma2(u2h2(t[d].w),     nw0, fW);
            u3         = __hfma2(u2h2(t[d + 1].w), nw1, u3);
            __half2 s01 = __hadd2(__habs2(u0), __habs2(u1));
            __half2 s23 = __hadd2(__habs2(u2), __habs2(u3));
            acc2[d] = __hadd2(acc2[d], __hadd2(s01, s23));
        }

        // flush packed half accumulators to fp32 (every oct, as R11)
        #pragma unroll
        for (int d = 0; d < DG; d++) {
            float2 f = __half22float2(acc2[d]);
            accf[d] += f.x + f.y;
        }
    }

    // ---- write out[b, dlo+d, h, w] (d=11 written by both splits, same value) ----
    float* orow = out + (((long)b * D_ + dlo) * H_ + h) * W_ + w;
    #pragma unroll
    for (int d = 0; d < DG; d++)
        orow[(long)d * HW] = accf[d];
}

extern "C" void kernel_launch(void* const* d_in, const int* in_sizes, int n_in,
                              void* d_out, int out_size)
{
    (void)in_sizes; (void)n_in; (void)out_size;
    const float* feat_l = (const float*)d_in[0];
    const float* feat_r = (const float*)d_in[1];
    const float* disp   = (const float*)d_in[2];
    float* out = (float*)d_out;

    dim3 grid(4, H_, B_);     // 2 halves x 2 d-splits = 1024 thin CTAs
    cost_volume_kernel<<<grid, WT>>>(feat_l, feat_r, disp, out);
}

// round 17
// speedup vs baseline: 1.0632x; 1.0632x over previous
#include <cuda_runtime.h>
#include <cuda_fp16.h>
#include <cstring>

#define B_    2
#define C_    32
#define H_    128
#define W_    256
#define MAXD  12
#define D_    23            // 2*MAXD - 1
#define HW    (H_ * W_)
#define WT    128           // threads per CTA (half row)
#define NO    4             // channel octs of 8
#define SW2   220           // window: 76 left halo + 128 + 16 right
#define HALO  76
#define DG    12            // disparities per split (d=11 computed by both)
#define TAPS  13            // DG + 1

__device__ __forceinline__ __half2 u2h2(unsigned u) {
    __half2 r; memcpy(&r, &u, 4); return r;
}

struct FlcRaw { float a0, a1, a2, a3, b0, b1, b2, b3; };

__device__ __forceinline__ FlcRaw load_flc(const float* __restrict__ fl0, int o) {
    FlcRaw f;
    f.a0 = __ldg(fl0 + (2*o)      * HW);
    f.a1 = __ldg(fl0 + (2*o + 1)  * HW);
    f.a2 = __ldg(fl0 + (2*o + 16) * HW);
    f.a3 = __ldg(fl0 + (2*o + 17) * HW);
    f.b0 = __ldg(fl0 + (2*o + 8)  * HW);
    f.b1 = __ldg(fl0 + (2*o + 9)  * HW);
    f.b2 = __ldg(fl0 + (2*o + 24) * HW);
    f.b3 = __ldg(fl0 + (2*o + 25) * HW);
    return f;
}

// out[b,d,h,w] = sum_c |feat_l[b,c,h,w] - (w0*fr[c,x0+d] + w1*fr[c,x0+d+1])|
// R11 scaffold (fp16 8-channel octs, 13 x LDS.128 gather, 1024 thin CTAs,
// symmetric d-splits, flush every oct) + the two independently ncu-positive
// mechanisms, combined and cleaned:
//  (a) warp-local residue-8 sort: LDS.128 runs as 4 subphases of 8 lanes;
//      sorting the warp's pixels by (xs & 7) and dealing rank r to lane
//      (r>>2)|((r&3)<<3) makes each subphase cover ~distinct 16B slots
//      (measured -14% crossbar busy in R13). Permutation stays in-warp ->
//      feat_l/out address sets unchanged, no scatter penalty.
//  (b) distance-1 feat_l prefetch: oct o+1's 8 LDG.32 issue under oct o's
//      math, removing the per-oct LDG->HFMA head bubble (R15).
__global__ __launch_bounds__(WT)
void cost_volume_kernel(const float* __restrict__ feat_l,
                        const float* __restrict__ feat_r,
                        const float* __restrict__ disp,
                        float* __restrict__ out)
{
    __shared__ __align__(16) uint4 s_o[NO][SW2];   // 14080 B
    __shared__ int s_src[4][32];                   // warp permutation bounce

    const int xb    = blockIdx.x;        // 0..3 : (spl<<1)|half
    const int half_ = xb & 1;
    const int spl   = xb >> 1;
    const int h     = blockIdx.y;
    const int b     = blockIdx.z;
    const int tid   = threadIdx.x;
    const int lane  = tid & 31;
    const int wid   = tid >> 5;
    const int W0    = half_ * WT;
    const int base  = W0 - HALO;         // global x of window index 0
    const int dlo   = spl * 11;          // 0 or 11

    // ---- stage zero-padded feat_r window as 8-channel octs (R11 fill) ----
    {
        const float* fr0 = feat_r + (((long)b * C_) * H_ + h) * W_;
        #pragma unroll
        for (int s = 0; s < 2; s++) {
            const int i = tid + s * WT;
            if (i < SW2) {
                const int gx = base + i;
                const bool v = (gx >= 0) & (gx < W_);
                const int gxc = v ? gx : 0;
                #pragma unroll
                for (int o = 0; o < NO; o++) {
                    const float a0 = v ? __ldg(fr0 + (2*o)      * HW + gxc) : 0.0f;
                    const float a1 = v ? __ldg(fr0 + (2*o + 1)  * HW + gxc) : 0.0f;
                    const float a2 = v ? __ldg(fr0 + (2*o + 16) * HW + gxc) : 0.0f;
                    const float a3 = v ? __ldg(fr0 + (2*o + 17) * HW + gxc) : 0.0f;
                    const float b0 = v ? __ldg(fr0 + (2*o + 8)  * HW + gxc) : 0.0f;
                    const float b1 = v ? __ldg(fr0 + (2*o + 9)  * HW + gxc) : 0.0f;
                    const float b2 = v ? __ldg(fr0 + (2*o + 24) * HW + gxc) : 0.0f;
                    const float b3 = v ? __ldg(fr0 + (2*o + 25) * HW + gxc) : 0.0f;
                    __half2 px = __floats2half2_rn(a0, a2);
                    __half2 py = __floats2half2_rn(a1, a3);
                    __half2 pz = __floats2half2_rn(b0, b2);
                    __half2 pw = __floats2half2_rn(b1, b3);
                    uint4 ov;
                    memcpy(&ov.x, &px, 4); memcpy(&ov.y, &py, 4);
                    memcpy(&ov.z, &pz, 4); memcpy(&ov.w, &pw, 4);
                    s_o[o][i] = ov;
                }
            }
        }
    }

    // ---- per-thread interpolation setup (own pixel) ----
    const int   wown = W0 + tid;
    const float dval = __ldg(disp + ((long)b * H_ + h) * W_ + wown);
    const float px0  = ((float)wown - dval) - (float)(MAXD - 1);
    const float xf   = floorf(px0);
    const float w1own = px0 - xf;
    int x0l = (int)xf - base;
    x0l = max(0, min(SW2 - 24, x0l));
    const int xsown = x0l + dlo;

    // ---- warp-local residue-8 sort (minimal form) ----
    int xs, wpix;
    float w1;
    {
        const int key = xsown & 7;
        unsigned lt = 0, eqmask = 0;
        #pragma unroll
        for (int v = 0; v < 8; v++) {
            const unsigned bv = __ballot_sync(0xffffffffu, key == v);
            if (v < key) lt += __popc(bv);
            else if (v == key) eqmask = bv;
        }
        const int rank = (int)lt + __popc(eqmask & ((1u << lane) - 1u));
        const int dest = (rank >> 2) | ((rank & 3) << 3);   // subphase deal
        s_src[wid][dest] = lane;
        __syncwarp();
        const int m = s_src[wid][lane];
        xs   = __shfl_sync(0xffffffffu, xsown, m);
        w1   = __shfl_sync(0xffffffffu, w1own, m);
        wpix = __shfl_sync(0xffffffffu, wown,  m);
    }

    const float w0 = 1.0f - w1;
    const __half2 nw0 = __float2half2_rn(-w0);
    const __half2 nw1 = __float2half2_rn(-w1);

    const float* fl0 = feat_l + (((long)b * C_) * H_ + h) * W_ + wpix;

    // prime the feat_l pipeline (8 LDGs in flight across the barrier)
    FlcRaw cur = load_flc(fl0, 0);

    __syncthreads();

    float accf[DG];
    #pragma unroll
    for (int d = 0; d < DG; d++) accf[d] = 0.0f;

    #pragma unroll 1
    for (int o = 0; o < NO; o++) {                 // 4 octs (8 channels each)
        FlcRaw nxt;
        if (o < NO - 1) nxt = load_flc(fl0, o + 1);   // distance-1 prefetch

        const __half2 fX = __floats2half2_rn(cur.a0, cur.a2);
        const __half2 fY = __floats2half2_rn(cur.a1, cur.a3);
        const __half2 fZ = __floats2half2_rn(cur.b0, cur.b2);
        const __half2 fW = __floats2half2_rn(cur.b1, cur.b3);

        const uint4* row = &s_o[o][xs];
        uint4 t[TAPS];
        #pragma unroll
        for (int j = 0; j < TAPS; j++) t[j] = row[j];   // 13 x LDS.128

        __half2 acc2[DG];
        #pragma unroll
        for (int d = 0; d < DG; d++) acc2[d] = __float2half2_rn(0.0f);

        #pragma unroll
        for (int d = 0; d < DG; d++) {
            __half2 u0 = __hfma2(u2h2(t[d].x),     nw0, fX);
            u0         = __hfma2(u2h2(t[d + 1].x), nw1, u0);
            __half2 u1 = __hfma2(u2h2(t[d].y),     nw0, fY);
            u1         = __hfma2(u2h2(t[d + 1].y), nw1, u1);
            __half2 u2 = __hfma2(u2h2(t[d].z),     nw0, fZ);
            u2         = __hfma2(u2h2(t[d + 1].z), nw1, u2);
            __half2 u3 = __hfma2(u2h2(t[d].w),     nw0, fW);
            u3         = __hfma2(u2h2(t[d + 1].w), nw1, u3);
            __half2 s01 = __hadd2(__habs2(u0), __habs2(u1));
            __half2 s23 = __hadd2(__habs2(u2), __habs2(u3));
            acc2[d] = __hadd2(acc2[d], __hadd2(s01, s23));
        }

        // flush packed half accumulators to fp32 (every oct, as R11)
        #pragma unroll
        for (int d = 0; d < DG; d++) {
            float2 f = __half22float2(acc2[d]);
            accf[d] += f.x + f.y;
        }

        cur = nxt;
    }

    // ---- write out[b, dlo+d, h, wpix] (same per-warp address set) ----
    float* orow = out + (((long)b * D_ + dlo) * H_ + h) * W_ + wpix;
    #pragma unroll
    for (int d = 0; d < DG; d++)
        orow[(long)d * HW] = accf[d];
}

extern "C" void kernel_launch(void* const* d_in, const int* in_sizes, int n_in,
                              void* d_out, int out_size)
{
    (void)in_sizes; (void)n_in; (void)out_size;
    const float* feat_l = (const float*)d_in[0];
    const float* feat_r = (const float*)d_in[1];
    const float* disp   = (const float*)d_in[2];
    float* out = (float*)d_out;

    dim3 grid(4, H_, B_);     // 2 halves x 2 d-splits = 1024 thin CTAs
    cost_volume_kernel<<<grid, WT>>>(feat_l, feat_r, disp, out);
}